// round 3
// baseline (speedup 1.0000x reference)
#include <cuda_runtime.h>
#include <cstdint>

// Problem dims
#define B_   32
#define S_   2048
#define H_   1024
#define U_   1024
#define MTOT (B_*S_)      // 65536 GEMM rows
#define BS_TOT (B_*S_)

// GEMM tiling (Ampere-style mma.sync, since harness targets plain sm_100: no tcgen05)
#define BM 128
#define BN 128
#define BK 32
#define NIT (H_/BK)            // 32 mainloop iterations
#define AS_STRIDE 36           // A smem row stride (floats): banks (4*tr+tc) all distinct
#define BS_STRIDE 136          // B smem row stride (floats): banks (8*k+n) all distinct
#define A_FLOATS (BM*AS_STRIDE)        // 4608
#define B_FLOATS (BK*BS_STRIDE)        // 4352
#define STAGE_FLOATS (A_FLOATS+B_FLOATS) // 8960
#define STAGES 4
#define SMEM_MAIN_FLOATS (STAGES*STAGE_FLOATS)   // 35840 floats = 143360 B
#define SMEM_TOTAL ((SMEM_MAIN_FLOATS + 2*BN) * 4)  // + s_dp + s_v

#define NTILES (U_/BN)         // 8 N-tiles -> 8 score-partial slices

// ---------------- device scratch (static device arrays are allowed) ----------------
__device__ float g_dppart[8*B_*U_];          // dec_proj partial sums per k-split
__device__ float g_spart[NTILES*BS_TOT];     // score partials per N-tile (deterministic)
__device__ float g_attn[BS_TOT];

// ---------------- helpers ----------------
__device__ __forceinline__ uint32_t cvt_tf32(float x) {
    uint32_t r; asm("cvt.rna.tf32.f32 %0, %1;" : "=r"(r) : "f"(x)); return r;
}
__device__ __forceinline__ void mma_tf32(float* c, const uint32_t* a, const uint32_t* b) {
    asm volatile("mma.sync.aligned.m16n8k8.row.col.f32.tf32.tf32.f32 "
        "{%0,%1,%2,%3}, {%4,%5,%6,%7}, {%8,%9}, {%0,%1,%2,%3};"
        : "+f"(c[0]), "+f"(c[1]), "+f"(c[2]), "+f"(c[3])
        : "r"(a[0]), "r"(a[1]), "r"(a[2]), "r"(a[3]), "r"(b[0]), "r"(b[1]));
}
__device__ __forceinline__ void cp_async16(uint32_t smem_addr, const void* gptr) {
    asm volatile("cp.async.cg.shared.global [%0], [%1], 16;" :: "r"(smem_addr), "l"(gptr));
}
#define CP_ASYNC_COMMIT() asm volatile("cp.async.commit_group;" ::: "memory")
#define CP_ASYNC_WAIT2()  asm volatile("cp.async.wait_group 2;" ::: "memory")
#define CP_ASYNC_WAIT0()  asm volatile("cp.async.wait_group 0;" ::: "memory")

__device__ __forceinline__ uint32_t smem_u32(const void* p) {
    uint32_t a;
    asm("{ .reg .u64 t; cvta.to.shared.u64 t, %1; cvt.u32.u64 %0, t; }" : "=r"(a) : "l"(p));
    return a;
}

// Accurate fast tanh: 1 - 2/(e^{2x}+1). ~1e-6 error, robust at large |x|.
__device__ __forceinline__ float tanh_acc(float x) {
    float ex = __expf(2.0f * x);
    return 1.0f - __fdividef(2.0f, ex + 1.0f);
}

// ---------------- dec_proj partials ----------------
// g_dppart[ks][b][u] = sum_{k in split ks} dec[b][k] * W_a[k][u]
__global__ void k_decproj(const float* __restrict__ dec, const float* __restrict__ W_a) {
    __shared__ float sdec[B_][128];
    int u  = blockIdx.x * 128 + threadIdx.x;
    int k0 = blockIdx.y * 128;
    for (int i = threadIdx.x; i < B_ * 128; i += 128) {
        int b = i >> 7, kk = i & 127;
        sdec[b][kk] = dec[b * H_ + k0 + kk];
    }
    __syncthreads();
    float acc[B_];
    #pragma unroll
    for (int b = 0; b < B_; b++) acc[b] = 0.f;
    for (int kk = 0; kk < 128; kk++) {
        float w = W_a[(size_t)(k0 + kk) * U_ + u];
        #pragma unroll
        for (int b = 0; b < B_; b++) acc[b] = fmaf(sdec[b][kk], w, acc[b]);
    }
    float* dst = &g_dppart[blockIdx.y * (B_ * U_)];
    #pragma unroll
    for (int b = 0; b < B_; b++) dst[b * U_ + u] = acc[b];
}

// ---------------- main fused GEMM + tanh + v-dot ----------------
// Grid: (NTILES=8, M_tiles=512); N on x so the 8 CTAs sharing one A tile are
// launch-adjacent -> A comes mostly from L2. B (= W_a[H:], 4MB) is L2-resident.
__global__ void __launch_bounds__(256, 1) k_gemm_score(
    const float* __restrict__ enc, const float* __restrict__ W_a,
    const float* __restrict__ v_a, const float* __restrict__ b_a)
{
    extern __shared__ float sm[];
    const uint32_t sb = smem_u32(sm);
    const int tid = threadIdx.x;
    const int wid = tid >> 5, lane = tid & 31;
    const int wm = wid & 1, wn = wid >> 1;        // warp grid 2(M) x 4(N)
    const int tr = lane >> 2, tc = lane & 3;
    const int n0 = blockIdx.x * BN;
    const int m0 = blockIdx.y * BM;
    const int b  = m0 >> 11;                      // m0 / S_

    float* s_dp = sm + SMEM_MAIN_FLOATS;
    float* s_v  = s_dp + BN;
    for (int i = tid; i < BN; i += 256) {
        float dp = b_a[n0 + i];
        #pragma unroll
        for (int j = 0; j < 8; j++) dp += g_dppart[j * (B_ * U_) + b * U_ + n0 + i];
        s_dp[i] = dp;
        s_v[i]  = v_a[n0 + i];
    }

    const float* gA = enc + (size_t)m0 * H_;                   // [128 rows][1024]
    const float* gB = W_a + (size_t)H_ * U_ + (size_t)n0;      // [k][n] n-contig

    // async loads of one BK-chunk into stage st
    auto load_chunk = [&](int chunk) {
        const int st = chunk & 3;
        const uint32_t a_base = sb + (uint32_t)(st * STAGE_FLOATS) * 4u;
        const uint32_t b_base = a_base + A_FLOATS * 4u;
        const int k0 = chunk * BK;
        #pragma unroll
        for (int j = 0; j < 4; j++) {            // A: 128 rows x 8 chunks of 16B
            int idx = j * 256 + tid;
            int r = idx >> 3, c = idx & 7;
            cp_async16(a_base + (uint32_t)(r * (AS_STRIDE * 4) + c * 16),
                       gA + (size_t)r * H_ + k0 + c * 4);
        }
        #pragma unroll
        for (int j = 0; j < 4; j++) {            // B: 32 k-rows x 32 chunks of 16B
            int idx = j * 256 + tid;
            int kr = idx >> 5, c = idx & 31;
            cp_async16(b_base + (uint32_t)(kr * (BS_STRIDE * 4) + c * 16),
                       gB + (size_t)(k0 + kr) * U_ + c * 4);
        }
    };

    // prologue: stages 0..2
    #pragma unroll
    for (int c = 0; c < 3; c++) { load_chunk(c); CP_ASYNC_COMMIT(); }

    float acc[4][4][4];
    #pragma unroll
    for (int mi = 0; mi < 4; mi++)
        #pragma unroll
        for (int ni = 0; ni < 4; ni++)
            #pragma unroll
            for (int r = 0; r < 4; r++) acc[mi][ni][r] = 0.f;

    #pragma unroll 1
    for (int i = 0; i < NIT; i++) {
        CP_ASYNC_WAIT2();             // chunk i resident (3 pending -> 2)
        __syncthreads();              // all warps done with iter i-1; chunk i visible
        if (i + 3 < NIT) load_chunk(i + 3);   // overwrites stage (i-1)&3: safe
        CP_ASYNC_COMMIT();            // uniform group count (may be empty)

        const float* As = sm + (i & 3) * STAGE_FLOATS;
        const float* Bs = As + A_FLOATS;
        #pragma unroll
        for (int kk = 0; kk < BK; kk += 8) {
            uint32_t au[4][4], bu[4][2];
            #pragma unroll
            for (int mi = 0; mi < 4; mi++) {
                int r0 = (wm * 64 + mi * 16 + tr) * AS_STRIDE;
                au[mi][0] = cvt_tf32(As[r0 + kk + tc]);
                au[mi][1] = cvt_tf32(As[r0 + 8 * AS_STRIDE + kk + tc]);
                au[mi][2] = cvt_tf32(As[r0 + kk + tc + 4]);
                au[mi][3] = cvt_tf32(As[r0 + 8 * AS_STRIDE + kk + tc + 4]);
            }
            #pragma unroll
            for (int ni = 0; ni < 4; ni++) {
                int cn = wn * 32 + ni * 8 + tr;
                bu[ni][0] = cvt_tf32(Bs[(kk + tc) * BS_STRIDE + cn]);
                bu[ni][1] = cvt_tf32(Bs[(kk + tc + 4) * BS_STRIDE + cn]);
            }
            #pragma unroll
            for (int mi = 0; mi < 4; mi++)
                #pragma unroll
                for (int ni = 0; ni < 4; ni++)
                    mma_tf32(acc[mi][ni], au[mi], bu[ni]);
        }
    }
    CP_ASYNC_WAIT0();

    // epilogue: score partial per row = sum_n v[n] * tanh(D[m][n] + dp[n])
    float (*red)[BM] = (float (*)[BM])sm;   // [4 warp_n][128 rows]; overlays stage 0 (safe)
    #pragma unroll
    for (int mi = 0; mi < 4; mi++) {
        float s0 = 0.f, s1 = 0.f;
        #pragma unroll
        for (int ni = 0; ni < 4; ni++) {
            int c0 = wn * 32 + ni * 8 + 2 * tc;
            float dp0 = s_dp[c0], dp1 = s_dp[c0 + 1];
            float v0  = s_v[c0],  v1  = s_v[c0 + 1];
            s0 = fmaf(v0, tanh_acc(acc[mi][ni][0] + dp0), s0);
            s0 = fmaf(v1, tanh_acc(acc[mi][ni][1] + dp1), s0);
            s1 = fmaf(v0, tanh_acc(acc[mi][ni][2] + dp0), s1);
            s1 = fmaf(v1, tanh_acc(acc[mi][ni][3] + dp1), s1);
        }
        s0 += __shfl_xor_sync(0xffffffffu, s0, 1);
        s0 += __shfl_xor_sync(0xffffffffu, s0, 2);
        s1 += __shfl_xor_sync(0xffffffffu, s1, 1);
        s1 += __shfl_xor_sync(0xffffffffu, s1, 2);
        if (tc == 0) {
            int r0 = wm * 64 + mi * 16 + tr;
            red[wn][r0]     = s0;
            red[wn][r0 + 8] = s1;
        }
    }
    __syncthreads();
    if (tid < BM) {
        float s = red[0][tid] + red[1][tid] + red[2][tid] + red[3][tid];
        g_spart[(size_t)blockIdx.x * BS_TOT + m0 + tid] = s;
    }
}

// ---------------- softmax over S (per batch) ----------------
__global__ void k_softmax() {
    __shared__ float red[256];
    int b = blockIdx.x, tid = threadIdx.x;
    float vals[8];
    float mx = -1e30f;
    #pragma unroll
    for (int j = 0; j < 8; j++) {
        int m = b * S_ + j * 256 + tid;
        float s = 0.f;
        #pragma unroll
        for (int t = 0; t < NTILES; t++) s += g_spart[(size_t)t * BS_TOT + m];
        vals[j] = s;
        mx = fmaxf(mx, s);
    }
    red[tid] = mx; __syncthreads();
    for (int o = 128; o > 0; o >>= 1) { if (tid < o) red[tid] = fmaxf(red[tid], red[tid + o]); __syncthreads(); }
    mx = red[0]; __syncthreads();
    float sum = 0.f;
    #pragma unroll
    for (int j = 0; j < 8; j++) { vals[j] = __expf(vals[j] - mx); sum += vals[j]; }
    red[tid] = sum; __syncthreads();
    for (int o = 128; o > 0; o >>= 1) { if (tid < o) red[tid] += red[tid + o]; __syncthreads(); }
    float inv = 1.0f / red[0];
    #pragma unroll
    for (int j = 0; j < 8; j++) g_attn[b * S_ + j * 256 + tid] = vals[j] * inv;
}

// ---------------- context = sum_s attn[b,s] * enc[b,s,:] ----------------
__global__ void k_context(const float* __restrict__ enc, float* __restrict__ out) {
    __shared__ float sa[S_];
    int b = blockIdx.x;
    int h = blockIdx.y * 256 + threadIdx.x;
    for (int s = threadIdx.x; s < S_; s += 256) sa[s] = g_attn[b * S_ + s];
    __syncthreads();
    const float* e = enc + (size_t)b * S_ * H_ + h;
    float acc = 0.f;
    #pragma unroll 8
    for (int s = 0; s < S_; s++) acc = fmaf(sa[s], e[(size_t)s * H_], acc);
    out[b * H_ + h] = acc;
}

// ---------------- launch ----------------
extern "C" void kernel_launch(void* const* d_in, const int* in_sizes, int n_in,
                              void* d_out, int out_size) {
    const float* dec = (const float*)d_in[0];   // [32,1024]
    const float* enc = (const float*)d_in[1];   // [32,2048,1024]
    const float* W_a = (const float*)d_in[2];   // [2048,1024]
    const float* b_a = (const float*)d_in[3];   // [1024]
    const float* v_a = (const float*)d_in[4];   // [1024,1]
    // d_in[5] = b_v : softmax is shift-invariant -> drops out of the output
    float* out = (float*)d_out;                 // [32,1024] fp32

    cudaFuncSetAttribute(k_gemm_score, cudaFuncAttributeMaxDynamicSharedMemorySize, SMEM_TOTAL);

    k_decproj<<<dim3(U_ / 128, H_ / 128), 128>>>(dec, W_a);
    k_gemm_score<<<dim3(NTILES, MTOT / BM), 256, SMEM_TOTAL>>>(enc, W_a, v_a, b_a);
    k_softmax<<<B_, 256>>>();
    k_context<<<dim3(B_, H_ / 256), 256>>>(enc, out);
}

// round 4
// speedup vs baseline: 1.2696x; 1.2696x over previous
#include <cuda_runtime.h>
#include <cstdint>

// Problem dims
#define B_   32
#define S_   2048
#define H_   1024
#define U_   1024
#define MTOT (B_*S_)      // 65536 GEMM rows
#define BS_TOT (B_*S_)

// GEMM tiling (Ampere-style mma.sync; toolchain targets plain sm_100: no tcgen05)
#define BM 128
#define BN 256
#define BK 32
#define NIT (H_/BK)            // 32 mainloop iterations
#define AS_STRIDE 36           // A smem row stride (floats): banks (4*tr+tc) all distinct
#define BS_STRIDE 264          // B smem row stride (floats): banks (8*tc+tr) all distinct
#define A_FLOATS (BM*AS_STRIDE)          // 4608
#define B_FLOATS (BK*BS_STRIDE)          // 8448
#define STAGE_FLOATS (A_FLOATS+B_FLOATS) // 13056
#define STAGES 4
#define SMEM_MAIN_FLOATS (STAGES*STAGE_FLOATS)      // 52224 floats = 208896 B
#define SMEM_TOTAL ((SMEM_MAIN_FLOATS + 2*BN) * 4)  // + s_dp + s_v = 210944 B

#define NTILES (U_/BN)         // 4 N-tiles -> 4 score-partial slices
#define SSPLIT 8               // context-kernel S split

// ---------------- device scratch (static device arrays are allowed) ----------------
__device__ float g_dppart[8*B_*U_];          // dec_proj partial sums per k-split
__device__ float g_spart[NTILES*BS_TOT];     // score partials per N-tile (deterministic)
__device__ float g_attn[BS_TOT];
__device__ float g_ctxpart[SSPLIT*B_*H_];    // context partial sums per S-chunk

// ---------------- helpers ----------------
__device__ __forceinline__ uint32_t cvt_tf32(float x) {
    uint32_t r; asm("cvt.rna.tf32.f32 %0, %1;" : "=r"(r) : "f"(x)); return r;
}
__device__ __forceinline__ void mma_tf32(float* c, const uint32_t* a, const uint32_t* b) {
    asm volatile("mma.sync.aligned.m16n8k8.row.col.f32.tf32.tf32.f32 "
        "{%0,%1,%2,%3}, {%4,%5,%6,%7}, {%8,%9}, {%0,%1,%2,%3};"
        : "+f"(c[0]), "+f"(c[1]), "+f"(c[2]), "+f"(c[3])
        : "r"(a[0]), "r"(a[1]), "r"(a[2]), "r"(a[3]), "r"(b[0]), "r"(b[1]));
}
__device__ __forceinline__ void cp_async16(uint32_t smem_addr, const void* gptr) {
    asm volatile("cp.async.cg.shared.global [%0], [%1], 16;" :: "r"(smem_addr), "l"(gptr));
}
#define CP_ASYNC_COMMIT() asm volatile("cp.async.commit_group;" ::: "memory")
#define CP_ASYNC_WAIT2()  asm volatile("cp.async.wait_group 2;" ::: "memory")
#define CP_ASYNC_WAIT0()  asm volatile("cp.async.wait_group 0;" ::: "memory")

__device__ __forceinline__ uint32_t smem_u32(const void* p) {
    uint32_t a;
    asm("{ .reg .u64 t; cvta.to.shared.u64 t, %1; cvt.u32.u64 %0, t; }" : "=r"(a) : "l"(p));
    return a;
}

// Accurate fast tanh: 1 - 2/(e^{2x}+1). ~1e-6 error, robust at large |x|.
__device__ __forceinline__ float tanh_acc(float x) {
    float ex = __expf(2.0f * x);
    return 1.0f - __fdividef(2.0f, ex + 1.0f);
}

// ---------------- dec_proj partials ----------------
// g_dppart[ks][b][u] = sum_{k in split ks} dec[b][k] * W_a[k][u]
__global__ void k_decproj(const float* __restrict__ dec, const float* __restrict__ W_a) {
    __shared__ float sdec[B_][128];
    int u  = blockIdx.x * 128 + threadIdx.x;
    int k0 = blockIdx.y * 128;
    for (int i = threadIdx.x; i < B_ * 128; i += 128) {
        int b = i >> 7, kk = i & 127;
        sdec[b][kk] = dec[b * H_ + k0 + kk];
    }
    __syncthreads();
    float acc[B_];
    #pragma unroll
    for (int b = 0; b < B_; b++) acc[b] = 0.f;
    for (int kk = 0; kk < 128; kk++) {
        float w = W_a[(size_t)(k0 + kk) * U_ + u];
        #pragma unroll
        for (int b = 0; b < B_; b++) acc[b] = fmaf(sdec[b][kk], w, acc[b]);
    }
    float* dst = &g_dppart[blockIdx.y * (B_ * U_)];
    #pragma unroll
    for (int b = 0; b < B_; b++) dst[b * U_ + u] = acc[b];
}

// ---------------- main fused GEMM + tanh + v-dot ----------------
// CTA tile 128x256, 8 warps as 2(M)x4(N), warp tile 64x64 (128 accums/thread).
// Grid: (NTILES=4, M_tiles=512); N on x so CTAs sharing one A tile are adjacent.
__global__ void __launch_bounds__(256, 1) k_gemm_score(
    const float* __restrict__ enc, const float* __restrict__ W_a,
    const float* __restrict__ v_a, const float* __restrict__ b_a)
{
    extern __shared__ float sm[];
    const uint32_t sb = smem_u32(sm);
    const int tid = threadIdx.x;
    const int wid = tid >> 5, lane = tid & 31;
    const int wm = wid & 1, wn = wid >> 1;        // warp grid 2(M) x 4(N)
    const int tr = lane >> 2, tc = lane & 3;
    const int n0 = blockIdx.x * BN;
    const int m0 = blockIdx.y * BM;
    const int b  = m0 >> 11;                      // m0 / S_

    float* s_dp = sm + SMEM_MAIN_FLOATS;
    float* s_v  = s_dp + BN;
    for (int i = tid; i < BN; i += 256) {
        float dp = b_a[n0 + i];
        #pragma unroll
        for (int j = 0; j < 8; j++) dp += g_dppart[j * (B_ * U_) + b * U_ + n0 + i];
        s_dp[i] = dp;
        s_v[i]  = v_a[n0 + i];
    }

    const float* gA = enc + (size_t)m0 * H_;                   // [128 rows][1024]
    const float* gB = W_a + (size_t)H_ * U_ + (size_t)n0;      // [k][n] n-contig

    // async loads of one BK-chunk into stage (chunk & 3)
    auto load_chunk = [&](int chunk) {
        const int st = chunk & 3;
        const uint32_t a_base = sb + (uint32_t)(st * STAGE_FLOATS) * 4u;
        const uint32_t b_base = a_base + A_FLOATS * 4u;
        const int k0 = chunk * BK;
        #pragma unroll
        for (int j = 0; j < 4; j++) {            // A: 128 rows x 8 chunks of 16B
            int idx = j * 256 + tid;
            int r = idx >> 3, c = idx & 7;
            cp_async16(a_base + (uint32_t)(r * (AS_STRIDE * 4) + c * 16),
                       gA + (size_t)r * H_ + k0 + c * 4);
        }
        #pragma unroll
        for (int j = 0; j < 8; j++) {            // B: 32 k-rows x 64 chunks of 16B
            int idx = j * 256 + tid;
            int kr = idx >> 6, c = idx & 63;
            cp_async16(b_base + (uint32_t)(kr * (BS_STRIDE * 4) + c * 16),
                       gB + (size_t)(k0 + kr) * U_ + c * 4);
        }
    };

    // prologue: stages 0..2
    #pragma unroll
    for (int c = 0; c < 3; c++) { load_chunk(c); CP_ASYNC_COMMIT(); }

    float acc[4][8][4];
    #pragma unroll
    for (int mi = 0; mi < 4; mi++)
        #pragma unroll
        for (int ni = 0; ni < 8; ni++)
            #pragma unroll
            for (int r = 0; r < 4; r++) acc[mi][ni][r] = 0.f;

    #pragma unroll 1
    for (int i = 0; i < NIT; i++) {
        CP_ASYNC_WAIT2();             // chunk i resident (3 pending -> 2)
        __syncthreads();              // all warps done with iter i-1; chunk i visible
        if (i + 3 < NIT) load_chunk(i + 3);   // overwrites stage (i-1)&3: safe
        CP_ASYNC_COMMIT();            // uniform group count (may be empty)

        const float* As = sm + (i & 3) * STAGE_FLOATS;
        const float* Bs = As + A_FLOATS;
        #pragma unroll
        for (int kk = 0; kk < BK; kk += 8) {
            uint32_t au[4][4], bu[8][2];
            #pragma unroll
            for (int mi = 0; mi < 4; mi++) {
                int r0 = (wm * 64 + mi * 16 + tr) * AS_STRIDE;
                au[mi][0] = cvt_tf32(As[r0 + kk + tc]);
                au[mi][1] = cvt_tf32(As[r0 + 8 * AS_STRIDE + kk + tc]);
                au[mi][2] = cvt_tf32(As[r0 + kk + tc + 4]);
                au[mi][3] = cvt_tf32(As[r0 + 8 * AS_STRIDE + kk + tc + 4]);
            }
            #pragma unroll
            for (int ni = 0; ni < 8; ni++) {
                int cn = wn * 64 + ni * 8 + tr;
                bu[ni][0] = cvt_tf32(Bs[(kk + tc) * BS_STRIDE + cn]);
                bu[ni][1] = cvt_tf32(Bs[(kk + tc + 4) * BS_STRIDE + cn]);
            }
            #pragma unroll
            for (int mi = 0; mi < 4; mi++)
                #pragma unroll
                for (int ni = 0; ni < 8; ni++)
                    mma_tf32(acc[mi][ni], au[mi], bu[ni]);
        }
    }
    CP_ASYNC_WAIT0();

    // epilogue: score partial per row = sum_n v[n] * tanh(D[m][n] + dp[n])
    float (*red)[BM] = (float (*)[BM])sm;   // [4 warp_n][128 rows]; overlays stage 0 (safe)
    #pragma unroll
    for (int mi = 0; mi < 4; mi++) {
        float s0 = 0.f, s1 = 0.f;
        #pragma unroll
        for (int ni = 0; ni < 8; ni++) {
            int c0 = wn * 64 + ni * 8 + 2 * tc;
            float dp0 = s_dp[c0], dp1 = s_dp[c0 + 1];
            float v0  = s_v[c0],  v1  = s_v[c0 + 1];
            s0 = fmaf(v0, tanh_acc(acc[mi][ni][0] + dp0), s0);
            s0 = fmaf(v1, tanh_acc(acc[mi][ni][1] + dp1), s0);
            s1 = fmaf(v0, tanh_acc(acc[mi][ni][2] + dp0), s1);
            s1 = fmaf(v1, tanh_acc(acc[mi][ni][3] + dp1), s1);
        }
        s0 += __shfl_xor_sync(0xffffffffu, s0, 1);
        s0 += __shfl_xor_sync(0xffffffffu, s0, 2);
        s1 += __shfl_xor_sync(0xffffffffu, s1, 1);
        s1 += __shfl_xor_sync(0xffffffffu, s1, 2);
        if (tc == 0) {
            int r0 = wm * 64 + mi * 16 + tr;
            red[wn][r0]     = s0;
            red[wn][r0 + 8] = s1;
        }
    }
    __syncthreads();
    if (tid < BM) {
        float s = red[0][tid] + red[1][tid] + red[2][tid] + red[3][tid];
        g_spart[(size_t)blockIdx.x * BS_TOT + m0 + tid] = s;
    }
}

// ---------------- softmax over S (per batch) ----------------
__global__ void k_softmax() {
    __shared__ float red[256];
    int b = blockIdx.x, tid = threadIdx.x;
    float vals[8];
    float mx = -1e30f;
    #pragma unroll
    for (int j = 0; j < 8; j++) {
        int m = b * S_ + j * 256 + tid;
        float s = 0.f;
        #pragma unroll
        for (int t = 0; t < NTILES; t++) s += g_spart[(size_t)t * BS_TOT + m];
        vals[j] = s;
        mx = fmaxf(mx, s);
    }
    red[tid] = mx; __syncthreads();
    for (int o = 128; o > 0; o >>= 1) { if (tid < o) red[tid] = fmaxf(red[tid], red[tid + o]); __syncthreads(); }
    mx = red[0]; __syncthreads();
    float sum = 0.f;
    #pragma unroll
    for (int j = 0; j < 8; j++) { vals[j] = __expf(vals[j] - mx); sum += vals[j]; }
    red[tid] = sum; __syncthreads();
    for (int o = 128; o > 0; o >>= 1) { if (tid < o) red[tid] += red[tid + o]; __syncthreads(); }
    float inv = 1.0f / red[0];
    #pragma unroll
    for (int j = 0; j < 8; j++) g_attn[b * S_ + j * 256 + tid] = vals[j] * inv;
}

// ---------------- context partials: sum over one S-chunk ----------------
// grid (B, H/256, SSPLIT); each CTA handles 256 h values over S/SSPLIT=256 rows.
__global__ void k_ctxpart(const float* __restrict__ enc) {
    __shared__ float sa[S_ / SSPLIT];
    const int b  = blockIdx.x;
    const int h  = blockIdx.y * 256 + threadIdx.x;
    const int s0 = blockIdx.z * (S_ / SSPLIT);
    for (int s = threadIdx.x; s < S_ / SSPLIT; s += 256) sa[s] = g_attn[b * S_ + s0 + s];
    __syncthreads();
    const float* e = enc + (size_t)b * S_ * H_ + (size_t)s0 * H_ + h;
    float acc = 0.f;
    #pragma unroll 16
    for (int s = 0; s < S_ / SSPLIT; s++) acc = fmaf(sa[s], e[(size_t)s * H_], acc);
    g_ctxpart[(size_t)blockIdx.z * (B_ * H_) + b * H_ + h] = acc;
}

// ---------------- final reduce of context partials ----------------
__global__ void k_ctxreduce(float* __restrict__ out) {
    int idx = blockIdx.x * 256 + threadIdx.x;
    float s = 0.f;
    #pragma unroll
    for (int j = 0; j < SSPLIT; j++) s += g_ctxpart[(size_t)j * (B_ * H_) + idx];
    out[idx] = s;
}

// ---------------- launch ----------------
extern "C" void kernel_launch(void* const* d_in, const int* in_sizes, int n_in,
                              void* d_out, int out_size) {
    const float* dec = (const float*)d_in[0];   // [32,1024]
    const float* enc = (const float*)d_in[1];   // [32,2048,1024]
    const float* W_a = (const float*)d_in[2];   // [2048,1024]
    const float* b_a = (const float*)d_in[3];   // [1024]
    const float* v_a = (const float*)d_in[4];   // [1024,1]
    // d_in[5] = b_v : softmax is shift-invariant -> drops out of the output
    float* out = (float*)d_out;                 // [32,1024] fp32

    cudaFuncSetAttribute(k_gemm_score, cudaFuncAttributeMaxDynamicSharedMemorySize, SMEM_TOTAL);

    k_decproj<<<dim3(U_ / 128, H_ / 128), 128>>>(dec, W_a);
    k_gemm_score<<<dim3(NTILES, MTOT / BM), 256, SMEM_TOTAL>>>(enc, W_a, v_a, b_a);
    k_softmax<<<B_, 256>>>();
    k_ctxpart<<<dim3(B_, H_ / 256, SSPLIT), 256>>>(enc);
    k_ctxreduce<<<(B_ * H_) / 256, 256>>>(out);
}

// round 5
// speedup vs baseline: 1.4917x; 1.1749x over previous
#include <cuda_runtime.h>
#include <cstdint>

// Problem dims
#define B_   32
#define S_   2048
#define H_   1024
#define U_   1024
#define MTOT (B_*S_)      // 65536 GEMM rows
#define BS_TOT (B_*S_)

// GEMM tiling (Ampere-style mma.sync; toolchain targets plain sm_100: no tcgen05)
#define BM 128
#define BN 256
#define BK 32
#define NIT (H_/BK)            // 32 mainloop iterations
#define AS_STRIDE 36           // A smem row stride (floats): banks (4*tr+tc) all distinct
#define BS_STRIDE 264          // B smem row stride (floats): banks (8*tc+tr) all distinct
#define A_FLOATS (BM*AS_STRIDE)          // 4608
#define B_FLOATS (BK*BS_STRIDE)          // 8448
#define STAGE_FLOATS (A_FLOATS+B_FLOATS) // 13056
#define STAGES 4
#define SMEM_MAIN_FLOATS (STAGES*STAGE_FLOATS)      // 52224 floats = 208896 B
#define SMEM_TOTAL ((SMEM_MAIN_FLOATS + 2*BN) * 4)  // + s_dp + s_v = 210944 B

#define NTILES (U_/BN)         // 4 N-tiles -> 4 score-partial slices
#define SSPLIT 16              // context-kernel S split
#define DPSPLIT 16             // dec_proj k split

// ---------------- device scratch (static device arrays are allowed) ----------------
__device__ float g_dppart[DPSPLIT*B_*U_];    // dec_proj partial sums per k-split
__device__ float g_spart[NTILES*BS_TOT];     // score partials per N-tile (deterministic)
__device__ float g_attn[BS_TOT];
__device__ float g_ctxpart[SSPLIT*B_*H_];    // context partial sums per S-chunk

// ---------------- helpers ----------------
// tf32 "fast path": feed raw fp32 bits; HW mma ignores the low 13 mantissa bits.
__device__ __forceinline__ uint32_t as_tf32(float x) { return __float_as_uint(x); }

__device__ __forceinline__ void mma_tf32(float* c, const uint32_t* a, const uint32_t* b) {
    asm volatile("mma.sync.aligned.m16n8k8.row.col.f32.tf32.tf32.f32 "
        "{%0,%1,%2,%3}, {%4,%5,%6,%7}, {%8,%9}, {%0,%1,%2,%3};"
        : "+f"(c[0]), "+f"(c[1]), "+f"(c[2]), "+f"(c[3])
        : "r"(a[0]), "r"(a[1]), "r"(a[2]), "r"(a[3]), "r"(b[0]), "r"(b[1]));
}
__device__ __forceinline__ void cp_async16(uint32_t smem_addr, const void* gptr) {
    asm volatile("cp.async.cg.shared.global [%0], [%1], 16;" :: "r"(smem_addr), "l"(gptr));
}
#define CP_ASYNC_COMMIT() asm volatile("cp.async.commit_group;" ::: "memory")
#define CP_ASYNC_WAIT2()  asm volatile("cp.async.wait_group 2;" ::: "memory")
#define CP_ASYNC_WAIT0()  asm volatile("cp.async.wait_group 0;" ::: "memory")

__device__ __forceinline__ uint32_t smem_u32(const void* p) {
    uint32_t a;
    asm("{ .reg .u64 t; cvta.to.shared.u64 t, %1; cvt.u32.u64 %0, t; }" : "=r"(a) : "l"(p));
    return a;
}

// Accurate fast tanh: 1 - 2/(e^{2x}+1). ~1e-6 error, robust at large |x|.
__device__ __forceinline__ float tanh_acc(float x) {
    float ex = __expf(2.0f * x);
    return 1.0f - __fdividef(2.0f, ex + 1.0f);
}

// ---------------- dec_proj partials ----------------
// g_dppart[ks][b][u] = sum_{k in split ks} dec[b][k] * W_a[k][u]
__global__ void k_decproj(const float* __restrict__ dec, const float* __restrict__ W_a) {
    __shared__ float sdec[B_][64];
    int u  = blockIdx.x * 128 + threadIdx.x;
    int k0 = blockIdx.y * 64;
    for (int i = threadIdx.x; i < B_ * 64; i += 128) {
        int b = i >> 6, kk = i & 63;
        sdec[b][kk] = dec[b * H_ + k0 + kk];
    }
    __syncthreads();
    float acc[B_];
    #pragma unroll
    for (int b = 0; b < B_; b++) acc[b] = 0.f;
    for (int kk = 0; kk < 64; kk++) {
        float w = W_a[(size_t)(k0 + kk) * U_ + u];
        #pragma unroll
        for (int b = 0; b < B_; b++) acc[b] = fmaf(sdec[b][kk], w, acc[b]);
    }
    float* dst = &g_dppart[blockIdx.y * (B_ * U_)];
    #pragma unroll
    for (int b = 0; b < B_; b++) dst[b * U_ + u] = acc[b];
}

// ---------------- main fused GEMM + tanh + v-dot ----------------
// CTA tile 128x256, 8 warps as 2(M)x4(N), warp tile 64x64 (128 accums/thread).
// Grid: (NTILES=4, M_tiles=512); N on x so CTAs sharing one A tile are adjacent.
__global__ void __launch_bounds__(256, 1) k_gemm_score(
    const float* __restrict__ enc, const float* __restrict__ W_a,
    const float* __restrict__ v_a, const float* __restrict__ b_a)
{
    extern __shared__ float sm[];
    const uint32_t sb = smem_u32(sm);
    const int tid = threadIdx.x;
    const int wid = tid >> 5, lane = tid & 31;
    const int wm = wid & 1, wn = wid >> 1;        // warp grid 2(M) x 4(N)
    const int tr = lane >> 2, tc = lane & 3;
    const int n0 = blockIdx.x * BN;
    const int m0 = blockIdx.y * BM;
    const int b  = m0 >> 11;                      // m0 / S_

    float* s_dp = sm + SMEM_MAIN_FLOATS;
    float* s_v  = s_dp + BN;
    for (int i = tid; i < BN; i += 256) {
        float dp = b_a[n0 + i];
        #pragma unroll
        for (int j = 0; j < DPSPLIT; j++) dp += g_dppart[j * (B_ * U_) + b * U_ + n0 + i];
        s_dp[i] = dp;
        s_v[i]  = v_a[n0 + i];
    }

    const float* gA = enc + (size_t)m0 * H_;                   // [128 rows][1024]
    const float* gB = W_a + (size_t)H_ * U_ + (size_t)n0;      // [k][n] n-contig

    // async loads of one BK-chunk into stage (chunk & 3)
    auto load_chunk = [&](int chunk) {
        const int st = chunk & 3;
        const uint32_t a_base = sb + (uint32_t)(st * STAGE_FLOATS) * 4u;
        const uint32_t b_base = a_base + A_FLOATS * 4u;
        const int k0 = chunk * BK;
        #pragma unroll
        for (int j = 0; j < 4; j++) {            // A: 128 rows x 8 chunks of 16B
            int idx = j * 256 + tid;
            int r = idx >> 3, c = idx & 7;
            cp_async16(a_base + (uint32_t)(r * (AS_STRIDE * 4) + c * 16),
                       gA + (size_t)r * H_ + k0 + c * 4);
        }
        #pragma unroll
        for (int j = 0; j < 8; j++) {            // B: 32 k-rows x 64 chunks of 16B
            int idx = j * 256 + tid;
            int kr = idx >> 6, c = idx & 63;
            cp_async16(b_base + (uint32_t)(kr * (BS_STRIDE * 4) + c * 16),
                       gB + (size_t)(k0 + kr) * U_ + c * 4);
        }
    };

    // prologue: stages 0..2
    #pragma unroll
    for (int c = 0; c < 3; c++) { load_chunk(c); CP_ASYNC_COMMIT(); }

    float acc[4][8][4];
    #pragma unroll
    for (int mi = 0; mi < 4; mi++)
        #pragma unroll
        for (int ni = 0; ni < 8; ni++)
            #pragma unroll
            for (int r = 0; r < 4; r++) acc[mi][ni][r] = 0.f;

    #pragma unroll 1
    for (int i = 0; i < NIT; i++) {
        CP_ASYNC_WAIT2();             // chunk i resident (3 pending -> 2)
        __syncthreads();              // all warps done with iter i-1; chunk i visible
        if (i + 3 < NIT) load_chunk(i + 3);   // overwrites stage (i-1)&3: safe
        CP_ASYNC_COMMIT();            // uniform group count (may be empty)

        const float* As = sm + (i & 3) * STAGE_FLOATS;
        const float* Bs = As + A_FLOATS;
        #pragma unroll
        for (int kk = 0; kk < BK; kk += 8) {
            uint32_t au[4][4], bu[8][2];
            #pragma unroll
            for (int mi = 0; mi < 4; mi++) {
                int r0 = (wm * 64 + mi * 16 + tr) * AS_STRIDE;
                au[mi][0] = as_tf32(As[r0 + kk + tc]);
                au[mi][1] = as_tf32(As[r0 + 8 * AS_STRIDE + kk + tc]);
                au[mi][2] = as_tf32(As[r0 + kk + tc + 4]);
                au[mi][3] = as_tf32(As[r0 + 8 * AS_STRIDE + kk + tc + 4]);
            }
            #pragma unroll
            for (int ni = 0; ni < 8; ni++) {
                int cn = wn * 64 + ni * 8 + tr;
                bu[ni][0] = as_tf32(Bs[(kk + tc) * BS_STRIDE + cn]);
                bu[ni][1] = as_tf32(Bs[(kk + tc + 4) * BS_STRIDE + cn]);
            }
            #pragma unroll
            for (int mi = 0; mi < 4; mi++)
                #pragma unroll
                for (int ni = 0; ni < 8; ni++)
                    mma_tf32(acc[mi][ni], au[mi], bu[ni]);
        }
    }
    CP_ASYNC_WAIT0();

    // epilogue: score partial per row = sum_n v[n] * tanh(D[m][n] + dp[n])
    float (*red)[BM] = (float (*)[BM])sm;   // [4 warp_n][128 rows]; overlays stage 0 (safe)
    #pragma unroll
    for (int mi = 0; mi < 4; mi++) {
        float s0 = 0.f, s1 = 0.f;
        #pragma unroll
        for (int ni = 0; ni < 8; ni++) {
            int c0 = wn * 64 + ni * 8 + 2 * tc;
            float dp0 = s_dp[c0], dp1 = s_dp[c0 + 1];
            float v0  = s_v[c0],  v1  = s_v[c0 + 1];
            s0 = fmaf(v0, tanh_acc(acc[mi][ni][0] + dp0), s0);
            s0 = fmaf(v1, tanh_acc(acc[mi][ni][1] + dp1), s0);
            s1 = fmaf(v0, tanh_acc(acc[mi][ni][2] + dp0), s1);
            s1 = fmaf(v1, tanh_acc(acc[mi][ni][3] + dp1), s1);
        }
        s0 += __shfl_xor_sync(0xffffffffu, s0, 1);
        s0 += __shfl_xor_sync(0xffffffffu, s0, 2);
        s1 += __shfl_xor_sync(0xffffffffu, s1, 1);
        s1 += __shfl_xor_sync(0xffffffffu, s1, 2);
        if (tc == 0) {
            int r0 = wm * 64 + mi * 16 + tr;
            red[wn][r0]     = s0;
            red[wn][r0 + 8] = s1;
        }
    }
    __syncthreads();
    if (tid < BM) {
        float s = red[0][tid] + red[1][tid] + red[2][tid] + red[3][tid];
        g_spart[(size_t)blockIdx.x * BS_TOT + m0 + tid] = s;
    }
}

// ---------------- softmax over S (per batch) ----------------
__global__ void k_softmax() {
    __shared__ float red[256];
    int b = blockIdx.x, tid = threadIdx.x;
    float vals[8];
    float mx = -1e30f;
    #pragma unroll
    for (int j = 0; j < 8; j++) {
        int m = b * S_ + j * 256 + tid;
        float s = 0.f;
        #pragma unroll
        for (int t = 0; t < NTILES; t++) s += g_spart[(size_t)t * BS_TOT + m];
        vals[j] = s;
        mx = fmaxf(mx, s);
    }
    red[tid] = mx; __syncthreads();
    for (int o = 128; o > 0; o >>= 1) { if (tid < o) red[tid] = fmaxf(red[tid], red[tid + o]); __syncthreads(); }
    mx = red[0]; __syncthreads();
    float sum = 0.f;
    #pragma unroll
    for (int j = 0; j < 8; j++) { vals[j] = __expf(vals[j] - mx); sum += vals[j]; }
    red[tid] = sum; __syncthreads();
    for (int o = 128; o > 0; o >>= 1) { if (tid < o) red[tid] += red[tid + o]; __syncthreads(); }
    float inv = 1.0f / red[0];
    #pragma unroll
    for (int j = 0; j < 8; j++) g_attn[b * S_ + j * 256 + tid] = vals[j] * inv;
}

// ---------------- context partials: sum over one S-chunk, float4 per thread ----------------
// grid (B, 1, SSPLIT); block 256; each thread owns 4 h-values, loops 128 s-rows.
#define SCHUNK (S_ / SSPLIT)    // 128
__global__ void k_ctxpart(const float* __restrict__ enc) {
    __shared__ float sa[SCHUNK];
    const int b  = blockIdx.x;
    const int s0 = blockIdx.z * SCHUNK;
    if (threadIdx.x < SCHUNK) sa[threadIdx.x] = g_attn[b * S_ + s0 + threadIdx.x];
    __syncthreads();
    const float4* e = (const float4*)(enc + (size_t)b * S_ * H_ + (size_t)s0 * H_) + threadIdx.x;
    float4 acc = make_float4(0.f, 0.f, 0.f, 0.f);
    #pragma unroll 8
    for (int s = 0; s < SCHUNK; s++) {
        float w = sa[s];
        float4 v = e[(size_t)s * (H_ / 4)];
        acc.x = fmaf(w, v.x, acc.x);
        acc.y = fmaf(w, v.y, acc.y);
        acc.z = fmaf(w, v.z, acc.z);
        acc.w = fmaf(w, v.w, acc.w);
    }
    float4* dst = (float4*)(g_ctxpart + (size_t)blockIdx.z * (B_ * H_) + b * H_) + threadIdx.x;
    *dst = acc;
}

// ---------------- final reduce of context partials ----------------
__global__ void k_ctxreduce(float* __restrict__ out) {
    int idx = blockIdx.x * 256 + threadIdx.x;
    float s = 0.f;
    #pragma unroll
    for (int j = 0; j < SSPLIT; j++) s += g_ctxpart[(size_t)j * (B_ * H_) + idx];
    out[idx] = s;
}

// ---------------- launch ----------------
extern "C" void kernel_launch(void* const* d_in, const int* in_sizes, int n_in,
                              void* d_out, int out_size) {
    const float* dec = (const float*)d_in[0];   // [32,1024]
    const float* enc = (const float*)d_in[1];   // [32,2048,1024]
    const float* W_a = (const float*)d_in[2];   // [2048,1024]
    const float* b_a = (const float*)d_in[3];   // [1024]
    const float* v_a = (const float*)d_in[4];   // [1024,1]
    // d_in[5] = b_v : softmax is shift-invariant -> drops out of the output
    float* out = (float*)d_out;                 // [32,1024] fp32

    cudaFuncSetAttribute(k_gemm_score, cudaFuncAttributeMaxDynamicSharedMemorySize, SMEM_TOTAL);

    k_decproj<<<dim3(U_ / 128, DPSPLIT), 128>>>(dec, W_a);
    k_gemm_score<<<dim3(NTILES, MTOT / BM), 256, SMEM_TOTAL>>>(enc, W_a, v_a, b_a);
    k_softmax<<<B_, 256>>>();
    k_ctxpart<<<dim3(B_, 1, SSPLIT), 256>>>(enc);
    k_ctxreduce<<<(B_ * H_) / 256, 256>>>(out);
}